// round 9
// baseline (speedup 1.0000x reference)
#include <cuda_runtime.h>
#include <cuda_bf16.h>
#include <cstdint>

// NODE forest via legacy-path tensor cores (mma.sync bf16, compiles for
// plain compute_103 PTX -- tcgen05 is sm_103a-feature-gated and the harness
// emits non-'a' PTX).
//
// logits[128,48] = x[128,64] @ W^T per CTA, 3-pass bf16 split
// (Ah*Wh + Ah*Wl + Al*Wh, fp32 accum). |z| <= TAU recomputed with the exact
// fp32 sequential chain (ascending-i FMA, bias after), bit = XLA rule
// fl(0.5 + 0.25 z) > 0.5. Split error <= ~3e-4 << TAU=2e-3, so all leaf
// indices are bit-identical to the reference.

#define THREADS 128
#define SPB 128
#define NBLK 8192
#define TAU 2e-3f

// ---- shared layout (bytes) ----
// xs  : f32[128][68]  = 34816 @ 0
// Wf  : f32[48][65]   = 12480 @ 34816
// Whp : u32[48][36]   =  6912 @ 47296   (bf16x2-packed hi W)
// Wlp : u32[48][36]   =  6912 @ 54208   (bf16x2-packed lo W)
// tbl : float2[512]   =  4096 @ 61120
// bs  : f32[48]       =   192 @ 65216
#define XS_OFF   0
#define WF_OFF   34816
#define WHP_OFF  47296
#define WLP_OFF  54208
#define TBL_OFF  61120
#define BS_OFF   65216
#define SMEM_BYTES 65408

static __device__ __forceinline__ uint32_t bf16x2_rn(float hi, float lo) {
    uint32_t r;
    asm("cvt.rn.bf16x2.f32 %0, %1, %2;" : "=r"(r) : "f"(hi), "f"(lo));
    return r;
}
// split a float2 into bf16x2 hi + bf16x2 residual lo ({v.x lo-half, v.y hi-half})
static __device__ __forceinline__ void split2(float vx, float vy,
                                              uint32_t& h, uint32_t& l) {
    h = bf16x2_rn(vy, vx);
    float h0 = __uint_as_float(h << 16);
    float h1 = __uint_as_float(h & 0xffff0000u);
    l = bf16x2_rn(vy - h1, vx - h0);
}
static __device__ __forceinline__ void mma_bf16(float* c, const uint32_t* a,
                                                const uint32_t* b) {
    asm("mma.sync.aligned.m16n8k16.row.col.f32.bf16.bf16.f32 "
        "{%0,%1,%2,%3}, {%4,%5,%6,%7}, {%8,%9}, {%0,%1,%2,%3};"
        : "+f"(c[0]), "+f"(c[1]), "+f"(c[2]), "+f"(c[3])
        : "r"(a[0]), "r"(a[1]), "r"(a[2]), "r"(a[3]), "r"(b[0]), "r"(b[1]));
}
static __device__ __forceinline__ int xla_bit(float z) {
    return __fadd_rn(0.5f, __fmul_rn(0.25f, z)) > 0.5f;
}

__global__ __launch_bounds__(THREADS, 2)
void node_forest_mma_kernel(const float*  __restrict__ x,      // [B,64]
                            const float*  __restrict__ Wsel,   // [48,64]
                            const float*  __restrict__ bsel,   // [48]
                            const float*  __restrict__ leafv,  // [8,64,2]
                            const float*  __restrict__ fcw,    // [2,16]
                            const float*  __restrict__ fcb,    // [2]
                            float2*       __restrict__ out)    // [B]
{
    extern __shared__ unsigned char smem[];
    float*    xs  = (float*)(smem + XS_OFF);
    float*    Wf  = (float*)(smem + WF_OFF);
    uint32_t* Whp = (uint32_t*)(smem + WHP_OFF);
    uint32_t* Wlp = (uint32_t*)(smem + WLP_OFF);
    float2*   tbl = (float2*)(smem + TBL_OFF);
    float*    bs  = (float*)(smem + BS_OFF);

    const int tid = threadIdx.x;

    // ---- stage x fp32 tile [128][68] ----
    const float4* xg = (const float4*)x + (size_t)blockIdx.x * (SPB * 16);
    #pragma unroll
    for (int it = 0; it < 16; ++it) {
        int f = tid + it * THREADS;
        float4 v = xg[f];
        int s = f >> 4, c4 = f & 15;
        *(float4*)(xs + s * 68 + c4 * 4) = v;
    }

    // ---- stage W: fp32 copy + bf16 hi/lo packed u32 tiles ----
    #pragma unroll
    for (int e = tid; e < 1536; e += THREADS) {
        int d = e >> 5, ip = e & 31;               // row d, u32-pair ip
        float w0 = Wsel[d * 64 + 2 * ip];
        float w1 = Wsel[d * 64 + 2 * ip + 1];
        Wf[d * 65 + 2 * ip]     = w0;
        Wf[d * 65 + 2 * ip + 1] = w1;
        uint32_t h, l;
        split2(w0, w1, h, l);
        Whp[d * 36 + ip] = h;
        Wlp[d * 36 + ip] = l;
    }

    // ---- fold leaf_values with fc_w; bias ----
    #pragma unroll
    for (int e = tid; e < 512; e += THREADS) {
        int t = e >> 6, leaf = e & 63;
        float l0 = leafv[t * 128 + leaf * 2 + 0];
        float l1 = leafv[t * 128 + leaf * 2 + 1];
        tbl[e] = make_float2(l0 * fcw[t * 2]      + l1 * fcw[t * 2 + 1],
                             l0 * fcw[16 + t * 2] + l1 * fcw[16 + t * 2 + 1]);
    }
    if (tid < 48) bs[tid] = bsel[tid];
    __syncthreads();

    const int lane = tid & 31, w = tid >> 5;
    const int g = lane >> 2, tig = lane & 3;

    float acc[2][6][4];
    #pragma unroll
    for (int m = 0; m < 2; ++m)
        #pragma unroll
        for (int n = 0; n < 6; ++n)
            #pragma unroll
            for (int q = 0; q < 4; ++q) acc[m][n][q] = 0.f;

    // ---- mainloop: 4 K-tiles x (2 M x 6 N) x 3 passes ----
    #pragma unroll
    for (int kt = 0; kt < 4; ++kt) {
        // B fragments (hi/lo) for all 6 N-tiles
        uint32_t bh[6][2], bl[6][2];
        #pragma unroll
        for (int n = 0; n < 6; ++n) {
            int nrow = n * 8 + g;
            int ip0 = nrow * 36 + kt * 8 + tig;
            bh[n][0] = Whp[ip0];     bh[n][1] = Whp[ip0 + 4];
            bl[n][0] = Wlp[ip0];     bl[n][1] = Wlp[ip0 + 4];
        }
        #pragma unroll
        for (int m = 0; m < 2; ++m) {
            int ra = w * 32 + m * 16 + g;
            int rb = ra + 8;
            int c0 = kt * 16 + tig * 2;
            uint32_t ah[4], al[4];
            float2 p;
            p = *(const float2*)(xs + ra * 68 + c0);     split2(p.x, p.y, ah[0], al[0]);
            p = *(const float2*)(xs + rb * 68 + c0);     split2(p.x, p.y, ah[1], al[1]);
            p = *(const float2*)(xs + ra * 68 + c0 + 8); split2(p.x, p.y, ah[2], al[2]);
            p = *(const float2*)(xs + rb * 68 + c0 + 8); split2(p.x, p.y, ah[3], al[3]);
            #pragma unroll
            for (int n = 0; n < 6; ++n) {
                mma_bf16(acc[m][n], ah, bh[n]);
                mma_bf16(acc[m][n], ah, bl[n]);
                mma_bf16(acc[m][n], al, bh[n]);
            }
        }
    }

    // ---- epilogue: bias, recompute band, bit masks ----
    unsigned long long mask[2][2] = {{0ull, 0ull}, {0ull, 0ull}};
    #pragma unroll
    for (int m = 0; m < 2; ++m) {
        #pragma unroll
        for (int half = 0; half < 2; ++half) {
            int row = w * 32 + m * 16 + half * 8 + g;
            #pragma unroll
            for (int n = 0; n < 6; ++n) {
                #pragma unroll
                for (int e = 0; e < 2; ++e) {
                    int col = n * 8 + tig * 2 + e;
                    float z = __fadd_rn(acc[m][n][2 * half + e], bs[col]);
                    if (fabsf(z) <= TAU) {
                        // exact fp32 chain (bit-faithful to reference)
                        const float* xr = xs + row * 68;
                        const float* wr = Wf + col * 65;
                        float a = 0.f;
                        #pragma unroll 1
                        for (int i = 0; i < 64; ++i)
                            a = __fmaf_rn(xr[i], wr[i], a);
                        z = __fadd_rn(a, bs[col]);
                    }
                    mask[m][half] |= ((unsigned long long)xla_bit(z)) << col;
                }
            }
        }
    }
    // OR across the quad (lanes tig=0..3 share rows)
    #pragma unroll
    for (int m = 0; m < 2; ++m)
        #pragma unroll
        for (int half = 0; half < 2; ++half) {
            unsigned long long v = mask[m][half];
            v |= __shfl_xor_sync(0xffffffffu, v, 1);
            v |= __shfl_xor_sync(0xffffffffu, v, 2);
            mask[m][half] = v;
        }

    // each lane finalizes one row: m = tig>>1, half = tig&1
    const unsigned long long mk = mask[tig >> 1][tig & 1];
    const int row = w * 32 + (tig >> 1) * 16 + (tig & 1) * 8 + g;
    float o0 = __ldg(&fcb[0]), o1 = __ldg(&fcb[1]);
    #pragma unroll
    for (int t = 0; t < 8; ++t) {
        int bits6 = (int)(mk >> (6 * t)) & 63;   // bit d = depth d
        int leaf = __brev((unsigned)bits6) >> 26; // depth 0 -> MSB of leaf
        float2 tv = tbl[t * 64 + leaf];
        o0 += tv.x;
        o1 += tv.y;
    }
    out[(size_t)blockIdx.x * SPB + row] = make_float2(o0, o1);
}

extern "C" void kernel_launch(void* const* d_in, const int* in_sizes, int n_in,
                              void* d_out, int out_size) {
    (void)in_sizes; (void)n_in; (void)out_size;
    cudaFuncSetAttribute(node_forest_mma_kernel,
                         cudaFuncAttributeMaxDynamicSharedMemorySize, SMEM_BYTES);
    cudaFuncSetAttribute(node_forest_mma_kernel,
                         cudaFuncAttributePreferredSharedMemoryCarveout, 100);
    node_forest_mma_kernel<<<NBLK, THREADS, SMEM_BYTES>>>(
        (const float*)d_in[0],   // x
        (const float*)d_in[1],   // W_sel
        (const float*)d_in[2],   // b_sel
        (const float*)d_in[3],   // leaf_values
        (const float*)d_in[4],   // fc_w
        (const float*)d_in[5],   // fc_b
        (float2*)d_out);
}

// round 10
// speedup vs baseline: 1.0598x; 1.0598x over previous
#include <cuda_runtime.h>
#include <cuda_bf16.h>
#include <cstdint>

// NODE forest via mma.sync bf16 (legacy tensor path, plain compute_103 PTX).
// R10: occupancy fix over R9 — no fp32 x/W staging in shared. A-fragments
// LDG'd directly from global x; the rare exact-recompute band (|z|<=TAU,
// ~0.12% of logits) reads x/W rows from global (L2-resident).
// smem 65KB -> 18KB, occupancy 2 -> ~10 warps/SMSP.
//
// Numerics: 3-pass bf16 split (Ah*Wh + Ah*Wl + Al*Wh, fp32 accum); error
// <= ~3e-4 << TAU=2e-3; band logits recomputed with the exact fp32
// ascending-i FMA chain, bias after, bit = fl(0.5 + 0.25 z) > 0.5 (XLA rule)
// -> leaf indices bit-identical to reference.

#define THREADS 128
#define SPB 128
#define NBLK 8192
#define TAU 2e-3f

// ---- shared layout (bytes) ----
// Whp : u32[48][36] = 6912  @ 0      (bf16x2-packed hi W, stride 36)
// Wlp : u32[48][36] = 6912  @ 6912   (bf16x2-packed lo W)
// tbl : float2[512] = 4096  @ 13824
// bs  : f32[48]     =  192  @ 17920
#define WHP_OFF  0
#define WLP_OFF  6912
#define TBL_OFF  13824
#define BS_OFF   17920
#define SMEM_BYTES 18112

static __device__ __forceinline__ uint32_t bf16x2_rn(float hi, float lo) {
    uint32_t r;
    asm("cvt.rn.bf16x2.f32 %0, %1, %2;" : "=r"(r) : "f"(hi), "f"(lo));
    return r;
}
static __device__ __forceinline__ void split2(float vx, float vy,
                                              uint32_t& h, uint32_t& l) {
    h = bf16x2_rn(vy, vx);
    float h0 = __uint_as_float(h << 16);
    float h1 = __uint_as_float(h & 0xffff0000u);
    l = bf16x2_rn(vy - h1, vx - h0);
}
static __device__ __forceinline__ void mma_bf16(float* c, const uint32_t* a,
                                                const uint32_t* b) {
    asm("mma.sync.aligned.m16n8k16.row.col.f32.bf16.bf16.f32 "
        "{%0,%1,%2,%3}, {%4,%5,%6,%7}, {%8,%9}, {%0,%1,%2,%3};"
        : "+f"(c[0]), "+f"(c[1]), "+f"(c[2]), "+f"(c[3])
        : "r"(a[0]), "r"(a[1]), "r"(a[2]), "r"(a[3]), "r"(b[0]), "r"(b[1]));
}
static __device__ __forceinline__ int xla_bit(float z) {
    return __fadd_rn(0.5f, __fmul_rn(0.25f, z)) > 0.5f;
}

__global__ __launch_bounds__(THREADS)
void node_forest_mma_kernel(const float*  __restrict__ x,      // [B,64]
                            const float*  __restrict__ Wsel,   // [48,64]
                            const float*  __restrict__ bsel,   // [48]
                            const float*  __restrict__ leafv,  // [8,64,2]
                            const float*  __restrict__ fcw,    // [2,16]
                            const float*  __restrict__ fcb,    // [2]
                            float2*       __restrict__ out)    // [B]
{
    extern __shared__ unsigned char smem[];
    uint32_t* Whp = (uint32_t*)(smem + WHP_OFF);
    uint32_t* Wlp = (uint32_t*)(smem + WLP_OFF);
    float2*   tbl = (float2*)(smem + TBL_OFF);
    float*    bs  = (float*)(smem + BS_OFF);

    const int tid = threadIdx.x;

    // ---- stage W: bf16 hi/lo packed u32 tiles (stride 36) ----
    #pragma unroll
    for (int e = tid; e < 1536; e += THREADS) {
        int d = e >> 5, ip = e & 31;
        float2 wp = *(const float2*)(Wsel + d * 64 + 2 * ip);
        uint32_t h, l;
        split2(wp.x, wp.y, h, l);
        Whp[d * 36 + ip] = h;
        Wlp[d * 36 + ip] = l;
    }
    // ---- fold leaf_values with fc_w; bias ----
    #pragma unroll
    for (int e = tid; e < 512; e += THREADS) {
        int t = e >> 6, leaf = e & 63;
        float l0 = leafv[t * 128 + leaf * 2 + 0];
        float l1 = leafv[t * 128 + leaf * 2 + 1];
        tbl[e] = make_float2(l0 * fcw[t * 2]      + l1 * fcw[t * 2 + 1],
                             l0 * fcw[16 + t * 2] + l1 * fcw[16 + t * 2 + 1]);
    }
    if (tid < 48) bs[tid] = bsel[tid];
    __syncthreads();

    const int lane = tid & 31, w = tid >> 5;
    const int g = lane >> 2, tig = lane & 3;
    const float* gx = x + (size_t)blockIdx.x * (SPB * 64);

    float acc[2][6][4];
    #pragma unroll
    for (int m = 0; m < 2; ++m)
        #pragma unroll
        for (int n = 0; n < 6; ++n)
            #pragma unroll
            for (int q = 0; q < 4; ++q) acc[m][n][q] = 0.f;

    // ---- mainloop: 4 K-tiles x (2 M x 6 N) x 3 passes ----
    #pragma unroll
    for (int kt = 0; kt < 4; ++kt) {
        uint32_t bh[6][2], bl[6][2];
        #pragma unroll
        for (int n = 0; n < 6; ++n) {
            int ip0 = (n * 8 + g) * 36 + kt * 8 + tig;
            bh[n][0] = Whp[ip0];  bh[n][1] = Whp[ip0 + 4];
            bl[n][0] = Wlp[ip0];  bl[n][1] = Wlp[ip0 + 4];
        }
        #pragma unroll
        for (int m = 0; m < 2; ++m) {
            int ra = w * 32 + m * 16 + g;
            int rb = ra + 8;
            int c0 = kt * 16 + tig * 2;
            uint32_t ah[4], al[4];
            float2 p;
            p = *(const float2*)(gx + ra * 64 + c0);     split2(p.x, p.y, ah[0], al[0]);
            p = *(const float2*)(gx + rb * 64 + c0);     split2(p.x, p.y, ah[1], al[1]);
            p = *(const float2*)(gx + ra * 64 + c0 + 8); split2(p.x, p.y, ah[2], al[2]);
            p = *(const float2*)(gx + rb * 64 + c0 + 8); split2(p.x, p.y, ah[3], al[3]);
            #pragma unroll
            for (int n = 0; n < 6; ++n) {
                mma_bf16(acc[m][n], ah, bh[n]);
                mma_bf16(acc[m][n], ah, bl[n]);
                mma_bf16(acc[m][n], al, bh[n]);
            }
        }
    }

    // ---- epilogue: bias, recompute band (global, rare), bit masks ----
    unsigned long long mask[2][2] = {{0ull, 0ull}, {0ull, 0ull}};
    #pragma unroll
    for (int m = 0; m < 2; ++m) {
        #pragma unroll
        for (int half = 0; half < 2; ++half) {
            int row = w * 32 + m * 16 + half * 8 + g;
            #pragma unroll
            for (int n = 0; n < 6; ++n) {
                #pragma unroll
                for (int e = 0; e < 2; ++e) {
                    int col = n * 8 + tig * 2 + e;
                    float z = __fadd_rn(acc[m][n][2 * half + e], bs[col]);
                    if (fabsf(z) <= TAU) {
                        const float* xr = gx + row * 64;
                        const float* wr = Wsel + col * 64;
                        float a = 0.f;
                        #pragma unroll 1
                        for (int i = 0; i < 64; ++i)
                            a = __fmaf_rn(__ldg(xr + i), __ldg(wr + i), a);
                        z = __fadd_rn(a, bs[col]);
                    }
                    mask[m][half] |= ((unsigned long long)xla_bit(z)) << col;
                }
            }
        }
    }
    #pragma unroll
    for (int m = 0; m < 2; ++m)
        #pragma unroll
        for (int half = 0; half < 2; ++half) {
            unsigned long long v = mask[m][half];
            v |= __shfl_xor_sync(0xffffffffu, v, 1);
            v |= __shfl_xor_sync(0xffffffffu, v, 2);
            mask[m][half] = v;
        }

    const unsigned long long mk = mask[tig >> 1][tig & 1];
    const int row = w * 32 + (tig >> 1) * 16 + (tig & 1) * 8 + g;
    float o0 = __ldg(&fcb[0]), o1 = __ldg(&fcb[1]);
    #pragma unroll
    for (int t = 0; t < 8; ++t) {
        int bits6 = (int)(mk >> (6 * t)) & 63;
        int leaf = __brev((unsigned)bits6) >> 26;
        float2 tv = tbl[t * 64 + leaf];
        o0 += tv.x;
        o1 += tv.y;
    }
    out[(size_t)blockIdx.x * SPB + row] = make_float2(o0, o1);
}

extern "C" void kernel_launch(void* const* d_in, const int* in_sizes, int n_in,
                              void* d_out, int out_size) {
    (void)in_sizes; (void)n_in; (void)out_size;
    cudaFuncSetAttribute(node_forest_mma_kernel,
                         cudaFuncAttributeMaxDynamicSharedMemorySize, SMEM_BYTES);
    node_forest_mma_kernel<<<NBLK, THREADS, SMEM_BYTES>>>(
        (const float*)d_in[0],   // x
        (const float*)d_in[1],   // W_sel
        (const float*)d_in[2],   // b_sel
        (const float*)d_in[3],   // leaf_values
        (const float*)d_in[4],   // fc_w
        (const float*)d_in[5],   // fc_b
        (float2*)d_out);
}